// round 14
// baseline (speedup 1.0000x reference)
#include <cuda_runtime.h>
#include <math.h>

// Problem constants
#define B_SZ    4
#define SEQ     2048
#define DIMM    1024
#define NHEAD   16
#define DHEAD   64
#define MLP_DIM 4096
#define ROWS    (B_SZ * SEQ)      // 8192
#define BHN     (B_SZ * NHEAD)    // 64

// ---------------------------------------------------------------------------
// Scratch (static device globals: allocation-free, graph-capture safe)
// ---------------------------------------------------------------------------
__device__ float g_h   [(size_t)ROWS * DIMM];          //  32 MB  (ln output, reused)
__device__ float g_qkv [(size_t)ROWS * 3 * DIMM];      //  96 MB
__device__ float g_S   [(size_t)BHN * SEQ * SEQ];      //   1 GB  attention scores
__device__ float g_attn[(size_t)ROWS * DIMM];          //  32 MB
__device__ float g_x2  [(size_t)ROWS * DIMM];          //  32 MB
__device__ float g_mid [(size_t)ROWS * MLP_DIM];       // 128 MB

// ---------------------------------------------------------------------------
// Reduction helpers
// ---------------------------------------------------------------------------
__device__ __forceinline__ float warp_sum(float v) {
#pragma unroll
    for (int o = 16; o > 0; o >>= 1) v += __shfl_xor_sync(0xffffffffu, v, o);
    return v;
}
__device__ __forceinline__ float warp_max(float v) {
#pragma unroll
    for (int o = 16; o > 0; o >>= 1) v = fmaxf(v, __shfl_xor_sync(0xffffffffu, v, o));
    return v;
}

__device__ __forceinline__ float gelu_exact(float v) {
    return 0.5f * v * (1.0f + erff(v * 0.7071067811865476f));
}

// ---------------------------------------------------------------------------
// LayerNorm: one block per row of 1024, 256 threads, float4 per thread
// ---------------------------------------------------------------------------
__global__ void __launch_bounds__(256) ln_kernel(const float* __restrict__ x,
                                                 const float* __restrict__ g,
                                                 const float* __restrict__ beta,
                                                 float* __restrict__ o) {
    __shared__ float red[8];
    const int tid = threadIdx.x;
    const size_t row = blockIdx.x;
    const float4 v = ((const float4*)(x + row * DIMM))[tid];

    float s = warp_sum(v.x + v.y + v.z + v.w);
    if ((tid & 31) == 0) red[tid >> 5] = s;
    __syncthreads();
    float tot = red[0];
#pragma unroll
    for (int i = 1; i < 8; i++) tot += red[i];
    const float mu = tot * (1.0f / (float)DIMM);

    const float4 d = make_float4(v.x - mu, v.y - mu, v.z - mu, v.w - mu);
    float sq = warp_sum(d.x * d.x + d.y * d.y + d.z * d.z + d.w * d.w);
    __syncthreads();
    if ((tid & 31) == 0) red[tid >> 5] = sq;
    __syncthreads();
    float vtot = red[0];
#pragma unroll
    for (int i = 1; i < 8; i++) vtot += red[i];
    const float rstd = rsqrtf(vtot * (1.0f / (float)DIMM) + 1e-5f);

    const float4 gv = ((const float4*)g)[tid];
    const float4 bv = ((const float4*)beta)[tid];
    float4 r;
    r.x = d.x * rstd * gv.x + bv.x;
    r.y = d.y * rstd * gv.y + bv.y;
    r.z = d.z * rstd * gv.z + bv.z;
    r.w = d.w * rstd * gv.w + bv.w;
    ((float4*)(o + row * DIMM))[tid] = r;
}

// ---------------------------------------------------------------------------
// Generic SGEMM: C[M,N] = A[M,K] @ B[K,N]  (row-major), 128x128x8 tiles,
// 256 threads, 8x8 microtile.
// EPI: 0 = none, 2 = +bias +residual, 3 = +bias +GELU(exact)
// M,N multiples of 128; K multiple of 8.
// ---------------------------------------------------------------------------
template <int EPI>
__global__ void __launch_bounds__(256) sgemm_kernel(const float* __restrict__ A,
                                                    const float* __restrict__ B,
                                                    const float* __restrict__ bias,
                                                    const float* __restrict__ res,
                                                    float* __restrict__ C,
                                                    int M, int N, int K) {
    __shared__ float As[8][128];
    __shared__ float Bs[8][128];
    const int tid = threadIdx.x;
    const int tileM = blockIdx.y * 128;
    const int tileN = blockIdx.x * 128;
    const int ty = tid >> 4;            // 0..15, rows ty*8
    const int tx = tid & 15;            // 0..15, cols tx*8

    const int aRow = tid >> 1;          // 0..127
    const int aCol = (tid & 1) * 4;     // 0 / 4
    const int bRow = tid >> 5;          // 0..7
    const int bCol = (tid & 31) * 4;    // 0..124

    const float* Aptr = A + (size_t)(tileM + aRow) * K + aCol;
    const float* Bptr = B + (size_t)bRow * N + tileN + bCol;

    float acc[8][8] = {};

    for (int k0 = 0; k0 < K; k0 += 8) {
        const float4 av = *(const float4*)(Aptr + k0);
        const float4 bv = *(const float4*)(Bptr + (size_t)k0 * N);
        __syncthreads();
        As[aCol + 0][aRow] = av.x;
        As[aCol + 1][aRow] = av.y;
        As[aCol + 2][aRow] = av.z;
        As[aCol + 3][aRow] = av.w;
        *(float4*)&Bs[bRow][bCol] = bv;
        __syncthreads();
#pragma unroll
        for (int kk = 0; kk < 8; kk++) {
            const float4 a0 = *(const float4*)&As[kk][ty * 8];
            const float4 a1 = *(const float4*)&As[kk][ty * 8 + 4];
            const float4 b0 = *(const float4*)&Bs[kk][tx * 8];
            const float4 b1 = *(const float4*)&Bs[kk][tx * 8 + 4];
            const float a[8] = {a0.x, a0.y, a0.z, a0.w, a1.x, a1.y, a1.z, a1.w};
            const float b[8] = {b0.x, b0.y, b0.z, b0.w, b1.x, b1.y, b1.z, b1.w};
#pragma unroll
            for (int i = 0; i < 8; i++)
#pragma unroll
                for (int j = 0; j < 8; j++) acc[i][j] += a[i] * b[j];
        }
    }

    float bias_reg[8];
    if (EPI >= 2) {
#pragma unroll
        for (int j = 0; j < 8; j++) bias_reg[j] = bias[tileN + tx * 8 + j];
    }

#pragma unroll
    for (int i = 0; i < 8; i++) {
        const size_t off = (size_t)(tileM + ty * 8 + i) * N + tileN + tx * 8;
        float vout[8];
#pragma unroll
        for (int j = 0; j < 8; j++) {
            float v = acc[i][j];
            if (EPI >= 2) v += bias_reg[j];
            if (EPI == 3) v = gelu_exact(v);
            vout[j] = v;
        }
        if (EPI == 2) {
            const float4 r0 = *(const float4*)(res + off);
            const float4 r1 = *(const float4*)(res + off + 4);
            vout[0] += r0.x; vout[1] += r0.y; vout[2] += r0.z; vout[3] += r0.w;
            vout[4] += r1.x; vout[5] += r1.y; vout[6] += r1.z; vout[7] += r1.w;
        }
        *(float4*)(C + off)     = make_float4(vout[0], vout[1], vout[2], vout[3]);
        *(float4*)(C + off + 4) = make_float4(vout[4], vout[5], vout[6], vout[7]);
    }
}

// ---------------------------------------------------------------------------
// QK^T scores: per (b,h), S[q,k] = scale * sum_d Q[q,d]*K[k,d]
// Q/K are strided views into qkv [8192, 3072]. 128x128 tiles, BK=32.
// grid: (keyTiles=16, qTiles=16, bh=64)
// ---------------------------------------------------------------------------
__global__ void __launch_bounds__(256) qk_kernel(const float* __restrict__ qkv,
                                                 float* __restrict__ S) {
    __shared__ float Qs[32][128];
    __shared__ float Ks[32][128];
    const int bh = blockIdx.z;
    const int b = bh >> 4, h = bh & 15;
    const float* Q  = qkv + (size_t)b * SEQ * (3 * DIMM) + h * DHEAD;
    const float* Kp = qkv + (size_t)b * SEQ * (3 * DIMM) + DIMM + h * DHEAD;
    const int tileM = blockIdx.y * 128;   // queries
    const int tileN = blockIdx.x * 128;   // keys
    const int tid = threadIdx.x;
    const int ty = tid >> 4, tx = tid & 15;

    float acc[8][8] = {};

    for (int kk = 0; kk < DHEAD; kk += 32) {
        float4 qv[4], kv[4];
#pragma unroll
        for (int i = 0; i < 4; i++) {
            const int idx = tid + i * 256;        // 0..1023
            const int r = idx >> 3;               // 0..127
            const int c4 = (idx & 7) * 4;         // 0..28
            qv[i] = *(const float4*)(Q  + (size_t)(tileM + r) * (3 * DIMM) + kk + c4);
            kv[i] = *(const float4*)(Kp + (size_t)(tileN + r) * (3 * DIMM) + kk + c4);
        }
        __syncthreads();
#pragma unroll
        for (int i = 0; i < 4; i++) {
            const int idx = tid + i * 256;
            const int r = idx >> 3;
            const int c4 = (idx & 7) * 4;
            Qs[c4 + 0][r] = qv[i].x; Qs[c4 + 1][r] = qv[i].y;
            Qs[c4 + 2][r] = qv[i].z; Qs[c4 + 3][r] = qv[i].w;
            Ks[c4 + 0][r] = kv[i].x; Ks[c4 + 1][r] = kv[i].y;
            Ks[c4 + 2][r] = kv[i].z; Ks[c4 + 3][r] = kv[i].w;
        }
        __syncthreads();
#pragma unroll
        for (int d = 0; d < 32; d++) {
            const float4 a0 = *(const float4*)&Qs[d][ty * 8];
            const float4 a1 = *(const float4*)&Qs[d][ty * 8 + 4];
            const float4 b0 = *(const float4*)&Ks[d][tx * 8];
            const float4 b1 = *(const float4*)&Ks[d][tx * 8 + 4];
            const float a[8] = {a0.x, a0.y, a0.z, a0.w, a1.x, a1.y, a1.z, a1.w};
            const float bb[8] = {b0.x, b0.y, b0.z, b0.w, b1.x, b1.y, b1.z, b1.w};
#pragma unroll
            for (int i = 0; i < 8; i++)
#pragma unroll
                for (int j = 0; j < 8; j++) acc[i][j] += a[i] * bb[j];
        }
    }

    const float scale = 0.125f;  // DHEAD^-0.5
    float* Sp = S + ((size_t)bh * SEQ + tileM) * SEQ + tileN;
#pragma unroll
    for (int i = 0; i < 8; i++) {
        float* row = Sp + (size_t)(ty * 8 + i) * SEQ + tx * 8;
        *(float4*)(row)     = make_float4(acc[i][0] * scale, acc[i][1] * scale,
                                          acc[i][2] * scale, acc[i][3] * scale);
        *(float4*)(row + 4) = make_float4(acc[i][4] * scale, acc[i][5] * scale,
                                          acc[i][6] * scale, acc[i][7] * scale);
    }
}

// ---------------------------------------------------------------------------
// Row softmax over 2048 cols. grid: (SEQ, BHN), 256 threads, 8 vals/thread.
// ---------------------------------------------------------------------------
__global__ void __launch_bounds__(256) softmax_kernel(float* __restrict__ S) {
    __shared__ float red[8];
    const int tid = threadIdx.x;
    float* p = S + ((size_t)blockIdx.y * SEQ + blockIdx.x) * SEQ;
    float4 v0 = ((float4*)p)[tid];
    float4 v1 = ((float4*)p)[tid + 256];

    float m = fmaxf(fmaxf(fmaxf(v0.x, v0.y), fmaxf(v0.z, v0.w)),
                    fmaxf(fmaxf(v1.x, v1.y), fmaxf(v1.z, v1.w)));
    m = warp_max(m);
    if ((tid & 31) == 0) red[tid >> 5] = m;
    __syncthreads();
    float gm = red[0];
#pragma unroll
    for (int i = 1; i < 8; i++) gm = fmaxf(gm, red[i]);

    v0.x = __expf(v0.x - gm); v0.y = __expf(v0.y - gm);
    v0.z = __expf(v0.z - gm); v0.w = __expf(v0.w - gm);
    v1.x = __expf(v1.x - gm); v1.y = __expf(v1.y - gm);
    v1.z = __expf(v1.z - gm); v1.w = __expf(v1.w - gm);

    float s = warp_sum(v0.x + v0.y + v0.z + v0.w + v1.x + v1.y + v1.z + v1.w);
    __syncthreads();
    if ((tid & 31) == 0) red[tid >> 5] = s;
    __syncthreads();
    float gs = red[0];
#pragma unroll
    for (int i = 1; i < 8; i++) gs += red[i];
    const float inv = 1.0f / gs;

    v0.x *= inv; v0.y *= inv; v0.z *= inv; v0.w *= inv;
    v1.x *= inv; v1.y *= inv; v1.z *= inv; v1.w *= inv;
    ((float4*)p)[tid] = v0;
    ((float4*)p)[tid + 256] = v1;
}

// ---------------------------------------------------------------------------
// PV: O[q,d] = sum_k P[q,k] * V[k,d] per (b,h). BM=128, BN=64, BK=16.
// grid: (qTiles=16, bh=64). Output written to attn [8192,1024] at col h*64.
// ---------------------------------------------------------------------------
__global__ void __launch_bounds__(256) pv_kernel(const float* __restrict__ qkv,
                                                 const float* __restrict__ S,
                                                 float* __restrict__ O) {
    __shared__ float As[16][128];  // P transposed
    __shared__ float Bs[16][64];   // V
    const int bh = blockIdx.y;
    const int b = bh >> 4, h = bh & 15;
    const float* P = S + (size_t)bh * SEQ * SEQ;
    const float* V = qkv + (size_t)b * SEQ * (3 * DIMM) + 2 * DIMM + h * DHEAD;
    const int tileM = blockIdx.x * 128;
    const int tid = threadIdx.x;
    const int ty = tid >> 4;   // rows ty*8
    const int tx = tid & 15;   // cols tx*4

    float acc[8][4] = {};

    for (int k0 = 0; k0 < SEQ; k0 += 16) {
        float4 pv[2];
#pragma unroll
        for (int i = 0; i < 2; i++) {
            const int idx = tid + i * 256;       // 0..511
            const int r = idx >> 2;              // 0..127
            const int c4 = (idx & 3) * 4;        // 0..12
            pv[i] = *(const float4*)(P + (size_t)(tileM + r) * SEQ + k0 + c4);
        }
        const int vr = tid >> 4;                 // 0..15
        const int vc4 = (tid & 15) * 4;          // 0..60
        const float4 vv = *(const float4*)(V + (size_t)(k0 + vr) * (3 * DIMM) + vc4);
        __syncthreads();
#pragma unroll
        for (int i = 0; i < 2; i++) {
            const int idx = tid + i * 256;
            const int r = idx >> 2;
            const int c4 = (idx & 3) * 4;
            As[c4 + 0][r] = pv[i].x; As[c4 + 1][r] = pv[i].y;
            As[c4 + 2][r] = pv[i].z; As[c4 + 3][r] = pv[i].w;
        }
        *(float4*)&Bs[vr][vc4] = vv;
        __syncthreads();
#pragma unroll
        for (int kk = 0; kk < 16; kk++) {
            const float4 a0 = *(const float4*)&As[kk][ty * 8];
            const float4 a1 = *(const float4*)&As[kk][ty * 8 + 4];
            const float4 bv = *(const float4*)&Bs[kk][tx * 4];
            const float a[8] = {a0.x, a0.y, a0.z, a0.w, a1.x, a1.y, a1.z, a1.w};
            const float bb[4] = {bv.x, bv.y, bv.z, bv.w};
#pragma unroll
            for (int i = 0; i < 8; i++)
#pragma unroll
                for (int j = 0; j < 4; j++) acc[i][j] += a[i] * bb[j];
        }
    }

#pragma unroll
    for (int i = 0; i < 8; i++) {
        float* Orow = O + (size_t)(b * SEQ + tileM + ty * 8 + i) * DIMM + h * DHEAD + tx * 4;
        *(float4*)Orow = make_float4(acc[i][0], acc[i][1], acc[i][2], acc[i][3]);
    }
}

// ---------------------------------------------------------------------------
// Launch
// ---------------------------------------------------------------------------
extern "C" void kernel_launch(void* const* d_in, const int* in_sizes, int n_in,
                              void* d_out, int out_size) {
    (void)in_sizes; (void)n_in; (void)out_size;
    const float* x     = (const float*)d_in[0];
    const float* ln1_g = (const float*)d_in[1];
    const float* ln1_b = (const float*)d_in[2];
    const float* w_qkv = (const float*)d_in[3];
    const float* w_out = (const float*)d_in[4];
    const float* b_out = (const float*)d_in[5];
    const float* ln2_g = (const float*)d_in[6];
    const float* ln2_b = (const float*)d_in[7];
    const float* w1    = (const float*)d_in[8];
    const float* b1    = (const float*)d_in[9];
    const float* w2    = (const float*)d_in[10];
    const float* b2    = (const float*)d_in[11];
    float* out = (float*)d_out;

    float *p_h, *p_qkv, *p_S, *p_attn, *p_x2, *p_mid;
    cudaGetSymbolAddress((void**)&p_h,    g_h);
    cudaGetSymbolAddress((void**)&p_qkv,  g_qkv);
    cudaGetSymbolAddress((void**)&p_S,    g_S);
    cudaGetSymbolAddress((void**)&p_attn, g_attn);
    cudaGetSymbolAddress((void**)&p_x2,   g_x2);
    cudaGetSymbolAddress((void**)&p_mid,  g_mid);

    // 1. h = LN1(x)
    ln_kernel<<<ROWS, 256>>>(x, ln1_g, ln1_b, p_h);
    // 2. qkv = h @ w_qkv                         [8192, 3072]
    sgemm_kernel<0><<<dim3(3 * DIMM / 128, ROWS / 128), 256>>>(
        p_h, w_qkv, nullptr, nullptr, p_qkv, ROWS, 3 * DIMM, DIMM);
    // 3. S = scale * Q @ K^T  per (b,h)          [64, 2048, 2048]
    qk_kernel<<<dim3(SEQ / 128, SEQ / 128, BHN), 256>>>(p_qkv, p_S);
    // 4. softmax rows
    softmax_kernel<<<dim3(SEQ, BHN), 256>>>(p_S);
    // 5. attn = P @ V  (heads concatenated)      [8192, 1024]
    pv_kernel<<<dim3(SEQ / 128, BHN), 256>>>(p_qkv, p_S, p_attn);
    // 6. x2 = attn @ w_out + b_out + x
    sgemm_kernel<2><<<dim3(DIMM / 128, ROWS / 128), 256>>>(
        p_attn, w_out, b_out, x, p_x2, ROWS, DIMM, DIMM);
    // 7. h = LN2(x2)
    ln_kernel<<<ROWS, 256>>>(p_x2, ln2_g, ln2_b, p_h);
    // 8. mid = gelu(h @ w1 + b1)                 [8192, 4096]
    sgemm_kernel<3><<<dim3(MLP_DIM / 128, ROWS / 128), 256>>>(
        p_h, w1, b1, nullptr, p_mid, ROWS, MLP_DIM, DIMM);
    // 9. out = mid @ w2 + b2 + x2
    sgemm_kernel<2><<<dim3(DIMM / 128, ROWS / 128), 256>>>(
        p_mid, w2, b2, p_x2, out, ROWS, DIMM, MLP_DIM);
}

// round 15
// speedup vs baseline: 1.0002x; 1.0002x over previous
#include <cuda_runtime.h>
#include <math.h>

// Problem constants
#define B_SZ    4
#define SEQ     2048
#define DIMM    1024
#define NHEAD   16
#define DHEAD   64
#define MLP_DIM 4096
#define ROWS    (B_SZ * SEQ)      // 8192
#define BHN     (B_SZ * NHEAD)    // 64

// ---------------------------------------------------------------------------
// Scratch (static device globals: allocation-free, graph-capture safe)
// ---------------------------------------------------------------------------
__device__ float g_h   [(size_t)ROWS * DIMM];          //  32 MB  (ln output, reused)
__device__ float g_qkv [(size_t)ROWS * 3 * DIMM];      //  96 MB
__device__ float g_S   [(size_t)BHN * SEQ * SEQ];      //   1 GB  attention scores
__device__ float g_attn[(size_t)ROWS * DIMM];          //  32 MB
__device__ float g_x2  [(size_t)ROWS * DIMM];          //  32 MB
__device__ float g_mid [(size_t)ROWS * MLP_DIM];       // 128 MB

// ---------------------------------------------------------------------------
// Reduction helpers
// ---------------------------------------------------------------------------
__device__ __forceinline__ float warp_sum(float v) {
#pragma unroll
    for (int o = 16; o > 0; o >>= 1) v += __shfl_xor_sync(0xffffffffu, v, o);
    return v;
}
__device__ __forceinline__ float warp_max(float v) {
#pragma unroll
    for (int o = 16; o > 0; o >>= 1) v = fmaxf(v, __shfl_xor_sync(0xffffffffu, v, o));
    return v;
}

__device__ __forceinline__ float gelu_exact(float v) {
    return 0.5f * v * (1.0f + erff(v * 0.7071067811865476f));
}

// ---------------------------------------------------------------------------
// LayerNorm: one block per row of 1024, 256 threads, float4 per thread
// ---------------------------------------------------------------------------
__global__ void __launch_bounds__(256) ln_kernel(const float* __restrict__ x,
                                                 const float* __restrict__ g,
                                                 const float* __restrict__ beta,
                                                 float* __restrict__ o) {
    __shared__ float red[8];
    const int tid = threadIdx.x;
    const size_t row = blockIdx.x;
    const float4 v = ((const float4*)(x + row * DIMM))[tid];

    float s = warp_sum(v.x + v.y + v.z + v.w);
    if ((tid & 31) == 0) red[tid >> 5] = s;
    __syncthreads();
    float tot = red[0];
#pragma unroll
    for (int i = 1; i < 8; i++) tot += red[i];
    const float mu = tot * (1.0f / (float)DIMM);

    const float4 d = make_float4(v.x - mu, v.y - mu, v.z - mu, v.w - mu);
    float sq = warp_sum(d.x * d.x + d.y * d.y + d.z * d.z + d.w * d.w);
    __syncthreads();
    if ((tid & 31) == 0) red[tid >> 5] = sq;
    __syncthreads();
    float vtot = red[0];
#pragma unroll
    for (int i = 1; i < 8; i++) vtot += red[i];
    const float rstd = rsqrtf(vtot * (1.0f / (float)DIMM) + 1e-5f);

    const float4 gv = ((const float4*)g)[tid];
    const float4 bv = ((const float4*)beta)[tid];
    float4 r;
    r.x = d.x * rstd * gv.x + bv.x;
    r.y = d.y * rstd * gv.y + bv.y;
    r.z = d.z * rstd * gv.z + bv.z;
    r.w = d.w * rstd * gv.w + bv.w;
    ((float4*)(o + row * DIMM))[tid] = r;
}

// ---------------------------------------------------------------------------
// Generic SGEMM: C[M,N] = A[M,K] @ B[K,N]  (row-major), 128x128x8 tiles,
// 256 threads, 8x8 microtile.
// EPI: 0 = none, 2 = +bias +residual, 3 = +bias +GELU(exact)
// M,N multiples of 128; K multiple of 8.
// ---------------------------------------------------------------------------
template <int EPI>
__global__ void __launch_bounds__(256) sgemm_kernel(const float* __restrict__ A,
                                                    const float* __restrict__ B,
                                                    const float* __restrict__ bias,
                                                    const float* __restrict__ res,
                                                    float* __restrict__ C,
                                                    int M, int N, int K) {
    __shared__ float As[8][128];
    __shared__ float Bs[8][128];
    const int tid = threadIdx.x;
    const int tileM = blockIdx.y * 128;
    const int tileN = blockIdx.x * 128;
    const int ty = tid >> 4;            // 0..15, rows ty*8
    const int tx = tid & 15;            // 0..15, cols tx*8

    const int aRow = tid >> 1;          // 0..127
    const int aCol = (tid & 1) * 4;     // 0 / 4
    const int bRow = tid >> 5;          // 0..7
    const int bCol = (tid & 31) * 4;    // 0..124

    const float* Aptr = A + (size_t)(tileM + aRow) * K + aCol;
    const float* Bptr = B + (size_t)bRow * N + tileN + bCol;

    float acc[8][8] = {};

    for (int k0 = 0; k0 < K; k0 += 8) {
        const float4 av = *(const float4*)(Aptr + k0);
        const float4 bv = *(const float4*)(Bptr + (size_t)k0 * N);
        __syncthreads();
        As[aCol + 0][aRow] = av.x;
        As[aCol + 1][aRow] = av.y;
        As[aCol + 2][aRow] = av.z;
        As[aCol + 3][aRow] = av.w;
        *(float4*)&Bs[bRow][bCol] = bv;
        __syncthreads();
#pragma unroll
        for (int kk = 0; kk < 8; kk++) {
            const float4 a0 = *(const float4*)&As[kk][ty * 8];
            const float4 a1 = *(const float4*)&As[kk][ty * 8 + 4];
            const float4 b0 = *(const float4*)&Bs[kk][tx * 8];
            const float4 b1 = *(const float4*)&Bs[kk][tx * 8 + 4];
            const float a[8] = {a0.x, a0.y, a0.z, a0.w, a1.x, a1.y, a1.z, a1.w};
            const float b[8] = {b0.x, b0.y, b0.z, b0.w, b1.x, b1.y, b1.z, b1.w};
#pragma unroll
            for (int i = 0; i < 8; i++)
#pragma unroll
                for (int j = 0; j < 8; j++) acc[i][j] += a[i] * b[j];
        }
    }

    float bias_reg[8];
    if (EPI >= 2) {
#pragma unroll
        for (int j = 0; j < 8; j++) bias_reg[j] = bias[tileN + tx * 8 + j];
    }

#pragma unroll
    for (int i = 0; i < 8; i++) {
        const size_t off = (size_t)(tileM + ty * 8 + i) * N + tileN + tx * 8;
        float vout[8];
#pragma unroll
        for (int j = 0; j < 8; j++) {
            float v = acc[i][j];
            if (EPI >= 2) v += bias_reg[j];
            if (EPI == 3) v = gelu_exact(v);
            vout[j] = v;
        }
        if (EPI == 2) {
            const float4 r0 = *(const float4*)(res + off);
            const float4 r1 = *(const float4*)(res + off + 4);
            vout[0] += r0.x; vout[1] += r0.y; vout[2] += r0.z; vout[3] += r0.w;
            vout[4] += r1.x; vout[5] += r1.y; vout[6] += r1.z; vout[7] += r1.w;
        }
        *(float4*)(C + off)     = make_float4(vout[0], vout[1], vout[2], vout[3]);
        *(float4*)(C + off + 4) = make_float4(vout[4], vout[5], vout[6], vout[7]);
    }
}

// ---------------------------------------------------------------------------
// QK^T scores: per (b,h), S[q,k] = scale * sum_d Q[q,d]*K[k,d]
// Q/K are strided views into qkv [8192, 3072]. 128x128 tiles, BK=32.
// grid: (keyTiles=16, qTiles=16, bh=64)
// ---------------------------------------------------------------------------
__global__ void __launch_bounds__(256) qk_kernel(const float* __restrict__ qkv,
                                                 float* __restrict__ S) {
    __shared__ float Qs[32][128];
    __shared__ float Ks[32][128];
    const int bh = blockIdx.z;
    const int b = bh >> 4, h = bh & 15;
    const float* Q  = qkv + (size_t)b * SEQ * (3 * DIMM) + h * DHEAD;
    const float* Kp = qkv + (size_t)b * SEQ * (3 * DIMM) + DIMM + h * DHEAD;
    const int tileM = blockIdx.y * 128;   // queries
    const int tileN = blockIdx.x * 128;   // keys
    const int tid = threadIdx.x;
    const int ty = tid >> 4, tx = tid & 15;

    float acc[8][8] = {};

    for (int kk = 0; kk < DHEAD; kk += 32) {
        float4 qv[4], kv[4];
#pragma unroll
        for (int i = 0; i < 4; i++) {
            const int idx = tid + i * 256;        // 0..1023
            const int r = idx >> 3;               // 0..127
            const int c4 = (idx & 7) * 4;         // 0..28
            qv[i] = *(const float4*)(Q  + (size_t)(tileM + r) * (3 * DIMM) + kk + c4);
            kv[i] = *(const float4*)(Kp + (size_t)(tileN + r) * (3 * DIMM) + kk + c4);
        }
        __syncthreads();
#pragma unroll
        for (int i = 0; i < 4; i++) {
            const int idx = tid + i * 256;
            const int r = idx >> 3;
            const int c4 = (idx & 7) * 4;
            Qs[c4 + 0][r] = qv[i].x; Qs[c4 + 1][r] = qv[i].y;
            Qs[c4 + 2][r] = qv[i].z; Qs[c4 + 3][r] = qv[i].w;
            Ks[c4 + 0][r] = kv[i].x; Ks[c4 + 1][r] = kv[i].y;
            Ks[c4 + 2][r] = kv[i].z; Ks[c4 + 3][r] = kv[i].w;
        }
        __syncthreads();
#pragma unroll
        for (int d = 0; d < 32; d++) {
            const float4 a0 = *(const float4*)&Qs[d][ty * 8];
            const float4 a1 = *(const float4*)&Qs[d][ty * 8 + 4];
            const float4 b0 = *(const float4*)&Ks[d][tx * 8];
            const float4 b1 = *(const float4*)&Ks[d][tx * 8 + 4];
            const float a[8] = {a0.x, a0.y, a0.z, a0.w, a1.x, a1.y, a1.z, a1.w};
            const float bb[8] = {b0.x, b0.y, b0.z, b0.w, b1.x, b1.y, b1.z, b1.w};
#pragma unroll
            for (int i = 0; i < 8; i++)
#pragma unroll
                for (int j = 0; j < 8; j++) acc[i][j] += a[i] * bb[j];
        }
    }

    const float scale = 0.125f;  // DHEAD^-0.5
    float* Sp = S + ((size_t)bh * SEQ + tileM) * SEQ + tileN;
#pragma unroll
    for (int i = 0; i < 8; i++) {
        float* row = Sp + (size_t)(ty * 8 + i) * SEQ + tx * 8;
        *(float4*)(row)     = make_float4(acc[i][0] * scale, acc[i][1] * scale,
                                          acc[i][2] * scale, acc[i][3] * scale);
        *(float4*)(row + 4) = make_float4(acc[i][4] * scale, acc[i][5] * scale,
                                          acc[i][6] * scale, acc[i][7] * scale);
    }
}

// ---------------------------------------------------------------------------
// Row softmax over 2048 cols. grid: (SEQ, BHN), 256 threads, 8 vals/thread.
// ---------------------------------------------------------------------------
__global__ void __launch_bounds__(256) softmax_kernel(float* __restrict__ S) {
    __shared__ float red[8];
    const int tid = threadIdx.x;
    float* p = S + ((size_t)blockIdx.y * SEQ + blockIdx.x) * SEQ;
    float4 v0 = ((float4*)p)[tid];
    float4 v1 = ((float4*)p)[tid + 256];

    float m = fmaxf(fmaxf(fmaxf(v0.x, v0.y), fmaxf(v0.z, v0.w)),
                    fmaxf(fmaxf(v1.x, v1.y), fmaxf(v1.z, v1.w)));
    m = warp_max(m);
    if ((tid & 31) == 0) red[tid >> 5] = m;
    __syncthreads();
    float gm = red[0];
#pragma unroll
    for (int i = 1; i < 8; i++) gm = fmaxf(gm, red[i]);

    v0.x = __expf(v0.x - gm); v0.y = __expf(v0.y - gm);
    v0.z = __expf(v0.z - gm); v0.w = __expf(v0.w - gm);
    v1.x = __expf(v1.x - gm); v1.y = __expf(v1.y - gm);
    v1.z = __expf(v1.z - gm); v1.w = __expf(v1.w - gm);

    float s = warp_sum(v0.x + v0.y + v0.z + v0.w + v1.x + v1.y + v1.z + v1.w);
    __syncthreads();
    if ((tid & 31) == 0) red[tid >> 5] = s;
    __syncthreads();
    float gs = red[0];
#pragma unroll
    for (int i = 1; i < 8; i++) gs += red[i];
    const float inv = 1.0f / gs;

    v0.x *= inv; v0.y *= inv; v0.z *= inv; v0.w *= inv;
    v1.x *= inv; v1.y *= inv; v1.z *= inv; v1.w *= inv;
    ((float4*)p)[tid] = v0;
    ((float4*)p)[tid + 256] = v1;
}

// ---------------------------------------------------------------------------
// PV: O[q,d] = sum_k P[q,k] * V[k,d] per (b,h). BM=128, BN=64, BK=16.
// grid: (qTiles=16, bh=64). Output written to attn [8192,1024] at col h*64.
// ---------------------------------------------------------------------------
__global__ void __launch_bounds__(256) pv_kernel(const float* __restrict__ qkv,
                                                 const float* __restrict__ S,
                                                 float* __restrict__ O) {
    __shared__ float As[16][128];  // P transposed
    __shared__ float Bs[16][64];   // V
    const int bh = blockIdx.y;
    const int b = bh >> 4, h = bh & 15;
    const float* P = S + (size_t)bh * SEQ * SEQ;
    const float* V = qkv + (size_t)b * SEQ * (3 * DIMM) + 2 * DIMM + h * DHEAD;
    const int tileM = blockIdx.x * 128;
    const int tid = threadIdx.x;
    const int ty = tid >> 4;   // rows ty*8
    const int tx = tid & 15;   // cols tx*4

    float acc[8][4] = {};

    for (int k0 = 0; k0 < SEQ; k0 += 16) {
        float4 pv[2];
#pragma unroll
        for (int i = 0; i < 2; i++) {
            const int idx = tid + i * 256;       // 0..511
            const int r = idx >> 2;              // 0..127
            const int c4 = (idx & 3) * 4;        // 0..12
            pv[i] = *(const float4*)(P + (size_t)(tileM + r) * SEQ + k0 + c4);
        }
        const int vr = tid >> 4;                 // 0..15
        const int vc4 = (tid & 15) * 4;          // 0..60
        const float4 vv = *(const float4*)(V + (size_t)(k0 + vr) * (3 * DIMM) + vc4);
        __syncthreads();
#pragma unroll
        for (int i = 0; i < 2; i++) {
            const int idx = tid + i * 256;
            const int r = idx >> 2;
            const int c4 = (idx & 3) * 4;
            As[c4 + 0][r] = pv[i].x; As[c4 + 1][r] = pv[i].y;
            As[c4 + 2][r] = pv[i].z; As[c4 + 3][r] = pv[i].w;
        }
        *(float4*)&Bs[vr][vc4] = vv;
        __syncthreads();
#pragma unroll
        for (int kk = 0; kk < 16; kk++) {
            const float4 a0 = *(const float4*)&As[kk][ty * 8];
            const float4 a1 = *(const float4*)&As[kk][ty * 8 + 4];
            const float4 bv = *(const float4*)&Bs[kk][tx * 4];
            const float a[8] = {a0.x, a0.y, a0.z, a0.w, a1.x, a1.y, a1.z, a1.w};
            const float bb[4] = {bv.x, bv.y, bv.z, bv.w};
#pragma unroll
            for (int i = 0; i < 8; i++)
#pragma unroll
                for (int j = 0; j < 4; j++) acc[i][j] += a[i] * bb[j];
        }
    }

#pragma unroll
    for (int i = 0; i < 8; i++) {
        float* Orow = O + (size_t)(b * SEQ + tileM + ty * 8 + i) * DIMM + h * DHEAD + tx * 4;
        *(float4*)Orow = make_float4(acc[i][0], acc[i][1], acc[i][2], acc[i][3]);
    }
}

// ---------------------------------------------------------------------------
// Launch
// ---------------------------------------------------------------------------
extern "C" void kernel_launch(void* const* d_in, const int* in_sizes, int n_in,
                              void* d_out, int out_size) {
    (void)in_sizes; (void)n_in; (void)out_size;
    const float* x     = (const float*)d_in[0];
    const float* ln1_g = (const float*)d_in[1];
    const float* ln1_b = (const float*)d_in[2];
    const float* w_qkv = (const float*)d_in[3];
    const float* w_out = (const float*)d_in[4];
    const float* b_out = (const float*)d_in[5];
    const float* ln2_g = (const float*)d_in[6];
    const float* ln2_b = (const float*)d_in[7];
    const float* w1    = (const float*)d_in[8];
    const float* b1    = (const float*)d_in[9];
    const float* w2    = (const float*)d_in[10];
    const float* b2    = (const float*)d_in[11];
    float* out = (float*)d_out;

    float *p_h, *p_qkv, *p_S, *p_attn, *p_x2, *p_mid;
    cudaGetSymbolAddress((void**)&p_h,    g_h);
    cudaGetSymbolAddress((void**)&p_qkv,  g_qkv);
    cudaGetSymbolAddress((void**)&p_S,    g_S);
    cudaGetSymbolAddress((void**)&p_attn, g_attn);
    cudaGetSymbolAddress((void**)&p_x2,   g_x2);
    cudaGetSymbolAddress((void**)&p_mid,  g_mid);

    // 1. h = LN1(x)
    ln_kernel<<<ROWS, 256>>>(x, ln1_g, ln1_b, p_h);
    // 2. qkv = h @ w_qkv                         [8192, 3072]
    sgemm_kernel<0><<<dim3(3 * DIMM / 128, ROWS / 128), 256>>>(
        p_h, w_qkv, nullptr, nullptr, p_qkv, ROWS, 3 * DIMM, DIMM);
    // 3. S = scale * Q @ K^T  per (b,h)          [64, 2048, 2048]
    qk_kernel<<<dim3(SEQ / 128, SEQ / 128, BHN), 256>>>(p_qkv, p_S);
    // 4. softmax rows
    softmax_kernel<<<dim3(SEQ, BHN), 256>>>(p_S);
    // 5. attn = P @ V  (heads concatenated)      [8192, 1024]
    pv_kernel<<<dim3(SEQ / 128, BHN), 256>>>(p_qkv, p_S, p_attn);
    // 6. x2 = attn @ w_out + b_out + x
    sgemm_kernel<2><<<dim3(DIMM / 128, ROWS / 128), 256>>>(
        p_attn, w_out, b_out, x, p_x2, ROWS, DIMM, DIMM);
    // 7. h = LN2(x2)
    ln_kernel<<<ROWS, 256>>>(p_x2, ln2_g, ln2_b, p_h);
    // 8. mid = gelu(h @ w1 + b1)                 [8192, 4096]
    sgemm_kernel<3><<<dim3(MLP_DIM / 128, ROWS / 128), 256>>>(
        p_h, w1, b1, nullptr, p_mid, ROWS, MLP_DIM, DIMM);
    // 9. out = mid @ w2 + b2 + x2
    sgemm_kernel<2><<<dim3(DIMM / 128, ROWS / 128), 256>>>(
        p_mid, w2, b2, p_x2, out, ROWS, DIMM, MLP_DIM);
}